// round 11
// baseline (speedup 1.0000x reference)
#include <cuda_runtime.h>
#include <math.h>

// Problem shape (fixed by the dataset): x [8, 4096, 1024] fp32
#define SEQ   4096
#define DIM   1024
#define BATCH 8
#define SD8   (SEQ * DIM / 8)   // 524,288 float8 (32B) chunks per batch slice

// Accurate sincos of (p_hi + p_lo), 0 <= p <= ~4096.
// fma-based Cody-Waite reduction mod pi/2, cephes minimax polys on |r|<=pi/4.
// Flag-independent (no libm sinf/cosf -> immune to --use_fast_math).
__device__ __forceinline__ void sincos_acc(float p_hi, float p_lo, float* so, float* co) {
    const float TWO_OVER_PI = 0.6366197723675814f;
    const float C1 =  1.57079637050628662109375f;   // (float)(pi/2)
    const float C2 = -4.3711390001862419e-8f;       // pi/2 - C1

    float q = rintf(p_hi * TWO_OVER_PI);
    int   j = (int)q;                                // 0 .. ~2608, non-negative
    float r = fmaf(q, -C1, p_hi);                    // exact-product fma reduction
    r = fmaf(q, -C2, r);
    r = r + p_lo;

    float z = r * r;

    // sin(r) ~= r + r*z*P(z)
    float sp = -1.9515295891e-4f;
    sp = fmaf(sp, z,  8.3321608736e-3f);
    sp = fmaf(sp, z, -1.6666654611e-1f);
    float sr = fmaf(sp * z, r, r);

    // cos(r) ~= 1 - z/2 + z*z*Q(z)
    float cp =  2.443315711809948e-5f;
    cp = fmaf(cp, z, -1.388731625493765e-3f);
    cp = fmaf(cp, z,  4.166664568298827e-2f);
    float cr = fmaf(cp, z * z, fmaf(-0.5f, z, 1.0f));

    int quad = j & 3;
    float ss = (quad == 0) ? sr : (quad == 1) ?  cr : (quad == 2) ? -sr : -cr;
    float cc = (quad == 0) ? cr : (quad == 1) ? -sr : (quad == 2) ? -cr :  sr;
    *so = ss;
    *co = cc;
}

// Compute the PE float4 for (s, d4): [sin(a0), cos(a0), sin(a1), cos(a1)]
__device__ __forceinline__ float4 pe_vec(unsigned s, unsigned d4) {
    const float pos = (float)s;

    // w_k = 10000^(-k/1024) = 2^(-k*L), L = log2(10000)/1024
    const float L    = 0.012976281620653759f;        // log2(10000)/1024
    const float LN2  = 0.6931471805599453f;
    const float RSTE = 0.9910458562488609f;          // 2^(-L)

    const float k0 = (float)(2u * d4);
    float eh = k0 * L;
    float el = fmaf(k0, L, -eh);                     // exact product tail
    float w0 = exp2f(-eh);
    w0 = fmaf(w0, -el * LN2, w0);                    // w0 *= 2^(-el) ~ (1 - el*ln2)
    float w1 = w0 * RSTE;

    // angle = pos * w as a double-float product
    float p0h = pos * w0;
    float p0l = fmaf(pos, w0, -p0h);
    float p1h = pos * w1;
    float p1l = fmaf(pos, w1, -p1h);

    float s0, c0, s1, c1;
    sincos_acc(p0h, p0l, &s0, &c0);
    sincos_acc(p1h, p1l, &s1, &c1);
    return make_float4(s0, c0, s1, c1);
}

struct F8 { float f[8]; };

// 256-bit streaming load/store (Blackwell native LDG.256/STG.256, .cs policy)
__device__ __forceinline__ F8 ldcs256(const float* p) {
    F8 r;
    asm volatile("ld.global.cs.v8.f32 {%0,%1,%2,%3,%4,%5,%6,%7}, [%8];"
                 : "=f"(r.f[0]), "=f"(r.f[1]), "=f"(r.f[2]), "=f"(r.f[3]),
                   "=f"(r.f[4]), "=f"(r.f[5]), "=f"(r.f[6]), "=f"(r.f[7])
                 : "l"(p));
    return r;
}
__device__ __forceinline__ void stcs256(float* p, const F8& v) {
    asm volatile("st.global.cs.v8.f32 [%0], {%1,%2,%3,%4,%5,%6,%7,%8};"
                 :: "l"(p),
                    "f"(v.f[0]), "f"(v.f[1]), "f"(v.f[2]), "f"(v.f[3]),
                    "f"(v.f[4]), "f"(v.f[5]), "f"(v.f[6]), "f"(v.f[7])
                 : "memory");
}

// R5 schedule with 256-bit memory ops: 128 threads/CTA, thread t owns the
// 32B chunk (d4 pair 2t, 2t+1) of one sequence row. Two 4-batch phases keep
// 128B in flight per thread (same as R5) at ~60 regs while halving the
// LDG/STG instruction count and L1tex queue entries.
__global__ void __launch_bounds__(128) pe_add_kernel(const float* __restrict__ x,
                                                     float* __restrict__ out) {
    const unsigned t    = threadIdx.x;                // 0..127
    const unsigned s    = blockIdx.x;                 // sequence position 0..4095
    const unsigned idx8 = s * 128u + t;               // float8 chunk index in a slice
    const unsigned off  = idx8 * 8u;                  // float offset

    // Phase 1: batches 0..3 — 4 x 256-bit streaming loads (128B in flight).
    F8 v0 = ldcs256(&x[0 * (SD8 * 8) + off]);
    F8 v1 = ldcs256(&x[1 * (SD8 * 8) + off]);
    F8 v2 = ldcs256(&x[2 * (SD8 * 8) + off]);
    F8 v3 = ldcs256(&x[3 * (SD8 * 8) + off]);

    // Trig for the 8 covered dims, computed while phase-1 loads are in flight.
    const float4 peA = pe_vec(s, 2u * t);             // dims 8t .. 8t+3
    const float4 peB = pe_vec(s, 2u * t + 1u);        // dims 8t+4 .. 8t+7
    float pe[8] = { peA.x, peA.y, peA.z, peA.w, peB.x, peB.y, peB.z, peB.w };

#pragma unroll
    for (int i = 0; i < 8; ++i) { v0.f[i] += pe[i]; v1.f[i] += pe[i];
                                  v2.f[i] += pe[i]; v3.f[i] += pe[i]; }
    stcs256(&out[0 * (SD8 * 8) + off], v0);
    stcs256(&out[1 * (SD8 * 8) + off], v1);
    stcs256(&out[2 * (SD8 * 8) + off], v2);
    stcs256(&out[3 * (SD8 * 8) + off], v3);

    // Phase 2: batches 4..7.
    F8 v4 = ldcs256(&x[4 * (SD8 * 8) + off]);
    F8 v5 = ldcs256(&x[5 * (SD8 * 8) + off]);
    F8 v6 = ldcs256(&x[6 * (SD8 * 8) + off]);
    F8 v7 = ldcs256(&x[7 * (SD8 * 8) + off]);

#pragma unroll
    for (int i = 0; i < 8; ++i) { v4.f[i] += pe[i]; v5.f[i] += pe[i];
                                  v6.f[i] += pe[i]; v7.f[i] += pe[i]; }
    stcs256(&out[4 * (SD8 * 8) + off], v4);
    stcs256(&out[5 * (SD8 * 8) + off], v5);
    stcs256(&out[6 * (SD8 * 8) + off], v6);
    stcs256(&out[7 * (SD8 * 8) + off], v7);
}

extern "C" void kernel_launch(void* const* d_in, const int* in_sizes, int n_in,
                              void* d_out, int out_size) {
    const float* x = (const float*)d_in[0];
    float* out = (float*)d_out;
    pe_add_kernel<<<SEQ, 128>>>(x, out);
}

// round 12
// speedup vs baseline: 1.0368x; 1.0368x over previous
#include <cuda_runtime.h>
#include <math.h>

// Problem shape (fixed by the dataset): x [8, 4096, 1024] fp32
#define SEQ   4096
#define DIM   1024
#define BATCH 8
#define SD4   (SEQ * DIM / 4)   // 1,048,576 float4 per batch slice

// ============================================================================
// FINAL — R5/R10 configuration, best measured twice: 43.5us total,
// 35.7-36.0us kernel, ~6.0 TB/s HBM (mixed R/W stream ceiling on sm_103a).
//
// Every design element validated experimentally across 11 rounds:
//  - pe[s,d] is batch-invariant: trig computed ONCE per (s,d4), applied to all
//    8 batch slices -> 8x trig amortization + 8-wide front-batched loads.
//  - d/d+1 share k=d//2: one angle yields both sin and cos.
//  - inv_freq via exp2f + fma tail (no init kernel: separate graph node cost
//    5us). Custom Cody-Waite sincos: accurate at args up to ~4096 rad
//    regardless of fast-math flags.
//  - Loads issued BEFORE trig: sincos chain hides under DRAM latency (-0.7us).
//  - .cs evict-first on both streams: best of all policies tested
//    (.cg loads, .wt stores both regressed).
//  - NO occupancy cap / NO persistent loop: both force regs < 64, split the
//    8-wide load batch, and cost ~3us (R3, R4).
//  - MLP=16 and 256-bit LDG.256/STG.256 both neutral (R6, R11): the HBM
//    channel, not the LSU/queue, is the binding constraint.
// ============================================================================

// Accurate sincos of (p_hi + p_lo), 0 <= p <= ~4096.
// fma-based Cody-Waite reduction mod pi/2, cephes minimax polys on |r|<=pi/4.
__device__ __forceinline__ void sincos_acc(float p_hi, float p_lo, float* so, float* co) {
    const float TWO_OVER_PI = 0.6366197723675814f;
    const float C1 =  1.57079637050628662109375f;   // (float)(pi/2)
    const float C2 = -4.3711390001862419e-8f;       // pi/2 - C1

    float q = rintf(p_hi * TWO_OVER_PI);
    int   j = (int)q;                                // 0 .. ~2608, non-negative
    float r = fmaf(q, -C1, p_hi);                    // exact-product fma reduction
    r = fmaf(q, -C2, r);
    r = r + p_lo;

    float z = r * r;

    // sin(r) ~= r + r*z*P(z)
    float sp = -1.9515295891e-4f;
    sp = fmaf(sp, z,  8.3321608736e-3f);
    sp = fmaf(sp, z, -1.6666654611e-1f);
    float sr = fmaf(sp * z, r, r);

    // cos(r) ~= 1 - z/2 + z*z*Q(z)
    float cp =  2.443315711809948e-5f;
    cp = fmaf(cp, z, -1.388731625493765e-3f);
    cp = fmaf(cp, z,  4.166664568298827e-2f);
    float cr = fmaf(cp, z * z, fmaf(-0.5f, z, 1.0f));

    int quad = j & 3;
    float ss = (quad == 0) ? sr : (quad == 1) ?  cr : (quad == 2) ? -sr : -cr;
    float cc = (quad == 0) ? cr : (quad == 1) ? -sr : (quad == 2) ? -cr :  sr;
    *so = ss;
    *co = cc;
}

// Compute the PE float4 for (s, d4): [sin(a0), cos(a0), sin(a1), cos(a1)]
__device__ __forceinline__ float4 pe_vec(unsigned s, unsigned d4) {
    const float pos = (float)s;

    // w_k = 10000^(-k/1024) = 2^(-k*L), L = log2(10000)/1024
    const float L    = 0.012976281620653759f;        // log2(10000)/1024
    const float LN2  = 0.6931471805599453f;
    const float RSTE = 0.9910458562488609f;          // 2^(-L)

    const float k0 = (float)(2u * d4);
    float eh = k0 * L;
    float el = fmaf(k0, L, -eh);                     // exact product tail
    float w0 = exp2f(-eh);
    w0 = fmaf(w0, -el * LN2, w0);                    // w0 *= 2^(-el) ~ (1 - el*ln2)
    float w1 = w0 * RSTE;

    // angle = pos * w as a double-float product
    float p0h = pos * w0;
    float p0l = fmaf(pos, w0, -p0h);
    float p1h = pos * w1;
    float p1l = fmaf(pos, w1, -p1h);

    float s0, c0, s1, c1;
    sincos_acc(p0h, p0l, &s0, &c0);
    sincos_acc(p1h, p1l, &s1, &c1);
    return make_float4(s0, c0, s1, c1);
}

__global__ void __launch_bounds__(256) pe_add_kernel(const float4* __restrict__ x,
                                                     float4* __restrict__ out) {
    const unsigned d4  = threadIdx.x;                 // float4 index along D (D/4 = 256)
    const unsigned s   = blockIdx.x;                  // sequence position 0..4095
    const unsigned idx = s * 256u + d4;

    // 8 front-batched streaming loads (MLP = 8), fully coalesced.
    float4 v[BATCH];
#pragma unroll
    for (int b = 0; b < BATCH; ++b)
        v[b] = __ldcs(&x[b * SD4 + idx]);             // evict-first: don't pollute L2

    // Trig computed while the loads are in flight.
    const float4 pe = pe_vec(s, d4);

#pragma unroll
    for (int b = 0; b < BATCH; ++b) {
        float4 t = v[b];
        t.x += pe.x; t.y += pe.y; t.z += pe.z; t.w += pe.w;
        __stcs(&out[b * SD4 + idx], t);               // streaming store, evict-first
    }
}

extern "C" void kernel_launch(void* const* d_in, const int* in_sizes, int n_in,
                              void* d_out, int out_size) {
    const float4* x = (const float4*)d_in[0];
    float4* out = (float4*)d_out;
    pe_add_kernel<<<SEQ, 256>>>(x, out);
}

// round 13
// speedup vs baseline: 1.0375x; 1.0007x over previous
#include <cuda_runtime.h>
#include <math.h>

// Problem shape (fixed by the dataset): x [8, 4096, 1024] fp32
#define SEQ   4096
#define DIM   1024
#define BATCH 8
#define SD4   (SEQ * DIM / 4)   // 1,048,576 float4 per batch slice

// ============================================================================
// FINAL — reproduced three times at 43.5us total / ~36us kernel / ~6.0 TB/s
// (the HBM3e mixed read/write stream ceiling on sm_103a).
//
// Every design element validated experimentally across 12 rounds:
//  - pe[s,d] is batch-invariant: trig computed ONCE per (s,d4), applied to all
//    8 batch slices -> 8x trig amortization + 8-wide front-batched loads.
//  - d/d+1 share k=d//2: one angle yields both sin and cos.
//  - inv_freq via exp2f + fma tail (no init kernel: a separate graph node
//    cost 5us). Custom Cody-Waite sincos: accurate at args up to ~4096 rad
//    regardless of fast-math compile flags.
//  - Loads issued BEFORE trig: sincos chain hides under DRAM latency (-0.7us).
//  - .cs evict-first on both streams: best of all policies tested
//    (.cg loads, .wt stores both regressed).
//  - NO occupancy cap / NO persistent loop: both force regs < 64, split the
//    8-wide load batch, and cost ~3us (R3, R4).
//  - MLP=16 and 256-bit LDG.256/STG.256 both neutral (R6, R11): the HBM
//    channel, not the LSU/queue, is the binding constraint.
// ============================================================================

// Accurate sincos of (p_hi + p_lo), 0 <= p <= ~4096.
// fma-based Cody-Waite reduction mod pi/2, cephes minimax polys on |r|<=pi/4.
__device__ __forceinline__ void sincos_acc(float p_hi, float p_lo, float* so, float* co) {
    const float TWO_OVER_PI = 0.6366197723675814f;
    const float C1 =  1.57079637050628662109375f;   // (float)(pi/2)
    const float C2 = -4.3711390001862419e-8f;       // pi/2 - C1

    float q = rintf(p_hi * TWO_OVER_PI);
    int   j = (int)q;                                // 0 .. ~2608, non-negative
    float r = fmaf(q, -C1, p_hi);                    // exact-product fma reduction
    r = fmaf(q, -C2, r);
    r = r + p_lo;

    float z = r * r;

    // sin(r) ~= r + r*z*P(z)
    float sp = -1.9515295891e-4f;
    sp = fmaf(sp, z,  8.3321608736e-3f);
    sp = fmaf(sp, z, -1.6666654611e-1f);
    float sr = fmaf(sp * z, r, r);

    // cos(r) ~= 1 - z/2 + z*z*Q(z)
    float cp =  2.443315711809948e-5f;
    cp = fmaf(cp, z, -1.388731625493765e-3f);
    cp = fmaf(cp, z,  4.166664568298827e-2f);
    float cr = fmaf(cp, z * z, fmaf(-0.5f, z, 1.0f));

    int quad = j & 3;
    float ss = (quad == 0) ? sr : (quad == 1) ?  cr : (quad == 2) ? -sr : -cr;
    float cc = (quad == 0) ? cr : (quad == 1) ? -sr : (quad == 2) ? -cr :  sr;
    *so = ss;
    *co = cc;
}

// Compute the PE float4 for (s, d4): [sin(a0), cos(a0), sin(a1), cos(a1)]
__device__ __forceinline__ float4 pe_vec(unsigned s, unsigned d4) {
    const float pos = (float)s;

    // w_k = 10000^(-k/1024) = 2^(-k*L), L = log2(10000)/1024
    const float L    = 0.012976281620653759f;        // log2(10000)/1024
    const float LN2  = 0.6931471805599453f;
    const float RSTE = 0.9910458562488609f;          // 2^(-L)

    const float k0 = (float)(2u * d4);
    float eh = k0 * L;
    float el = fmaf(k0, L, -eh);                     // exact product tail
    float w0 = exp2f(-eh);
    w0 = fmaf(w0, -el * LN2, w0);                    // w0 *= 2^(-el) ~ (1 - el*ln2)
    float w1 = w0 * RSTE;

    // angle = pos * w as a double-float product
    float p0h = pos * w0;
    float p0l = fmaf(pos, w0, -p0h);
    float p1h = pos * w1;
    float p1l = fmaf(pos, w1, -p1h);

    float s0, c0, s1, c1;
    sincos_acc(p0h, p0l, &s0, &c0);
    sincos_acc(p1h, p1l, &s1, &c1);
    return make_float4(s0, c0, s1, c1);
}

__global__ void __launch_bounds__(256) pe_add_kernel(const float4* __restrict__ x,
                                                     float4* __restrict__ out) {
    const unsigned d4  = threadIdx.x;                 // float4 index along D (D/4 = 256)
    const unsigned s   = blockIdx.x;                  // sequence position 0..4095
    const unsigned idx = s * 256u + d4;

    // 8 front-batched streaming loads (MLP = 8), fully coalesced.
    float4 v[BATCH];
#pragma unroll
    for (int b = 0; b < BATCH; ++b)
        v[b] = __ldcs(&x[b * SD4 + idx]);             // evict-first: don't pollute L2

    // Trig computed while the loads are in flight.
    const float4 pe = pe_vec(s, d4);

#pragma unroll
    for (int b = 0; b < BATCH; ++b) {
        float4 t = v[b];
        t.x += pe.x; t.y += pe.y; t.z += pe.z; t.w += pe.w;
        __stcs(&out[b * SD4 + idx], t);               // streaming store, evict-first
    }
}

extern "C" void kernel_launch(void* const* d_in, const int* in_sizes, int n_in,
                              void* d_out, int out_size) {
    const float4* x = (const float4*)d_in[0];
    float4* out = (float4*)d_out;
    pe_add_kernel<<<SEQ, 256>>>(x, out);
}